// round 15
// baseline (speedup 1.0000x reference)
#include <cuda_runtime.h>
#include <cuda_fp16.h>
#include <cstdint>

// Problem constants
#define B_  8
#define T_  1024
#define C_  768
#define H_  12
#define HS_ 64
#define M_  8192   // B*T

// ---------------------------------------------------------------------------
// Device-global scratch (no runtime allocation allowed)
// X, Y, weights, Q (prescaled 0.125), K, V(transposed [B,H,hs,T]): single fp16.
// ---------------------------------------------------------------------------
__device__ __half g_X [(size_t)M_*C_];
__device__ __half g_Y [(size_t)M_*C_];
__device__ __half g_Wa[(size_t)3*C_*C_];
__device__ __half g_Wp[(size_t)C_*C_];

__device__ __half g_Q [B_*H_*T_*HS_];
__device__ __half g_K [B_*H_*T_*HS_];
__device__ __half g_V [B_*H_*T_*HS_];

// ---------------------------------------------------------------------------
// Helpers (portable PTX only — compiles for plain sm_103 target)
// ---------------------------------------------------------------------------
__device__ __forceinline__ uint32_t smem_u32(const void* p){
    return (uint32_t)__cvta_generic_to_shared(p);
}
__device__ __forceinline__ void cpa16(uint32_t d, const void* s){
    asm volatile("cp.async.cg.shared.global [%0], [%1], 16;" :: "r"(d), "l"(s));
}
__device__ __forceinline__ void ldsm4(uint32_t& r0, uint32_t& r1,
                                      uint32_t& r2, uint32_t& r3, uint32_t a){
    asm volatile("ldmatrix.sync.aligned.m8n8.x4.shared.b16 {%0,%1,%2,%3}, [%4];"
                 : "=r"(r0), "=r"(r1), "=r"(r2), "=r"(r3) : "r"(a));
}
__device__ __forceinline__ void mma16816(float acc[4], const uint32_t a[4],
                                         const uint32_t b[2]){
    asm volatile(
        "mma.sync.aligned.m16n8k16.row.col.f32.f16.f16.f32 "
        "{%0,%1,%2,%3}, {%4,%5,%6,%7}, {%8,%9}, {%0,%1,%2,%3};"
        : "+f"(acc[0]), "+f"(acc[1]), "+f"(acc[2]), "+f"(acc[3])
        : "r"(a[0]), "r"(a[1]), "r"(a[2]), "r"(a[3]), "r"(b[0]), "r"(b[1]));
}
__device__ __forceinline__ uint32_t packhf(float x, float y){
    __half2 t = __float22half2_rn(make_float2(x, y));
    return *(uint32_t*)&t;
}

// per-lane ldmatrix row-offset helpers (byte offsets within a tile):
__device__ __forceinline__ uint32_t lm_offA(int lane, int rowb){
    return (uint32_t)(((lane & 7) + ((lane >> 3) & 1)*8) * rowb + (lane >> 4)*16);
}
__device__ __forceinline__ uint32_t lm_offB(int lane, int rowb){
    return (uint32_t)(((lane & 7) + (lane >> 4)*8) * rowb + ((lane >> 3) & 1)*16);
}

// ---------------------------------------------------------------------------
// Pre-pass: convert x fp32 -> single fp16
// ---------------------------------------------------------------------------
__global__ void convert_x(const float* __restrict__ src)
{
    const int i = blockIdx.x * blockDim.x + threadIdx.x;   // float4 index
    const int n4 = (M_*C_) / 4;
    if (i >= n4) return;
    const float4 v = ((const float4*)src)[i];
    ((uint32_t*)g_X)[i*2    ] = packhf(v.x, v.y);
    ((uint32_t*)g_X)[i*2 + 1] = packhf(v.z, v.w);
}

// ---------------------------------------------------------------------------
// Pre-pass: transpose weights -> [N][768] single fp16 (K-major)
// ---------------------------------------------------------------------------
template<int WHICH>
__global__ void transpose_w(const float* __restrict__ w)
{
    constexpr int N = (WHICH == 0) ? 3*C_ : C_;
    __half* Hh = (WHICH == 0) ? g_Wa : g_Wp;

    __shared__ float tile[32][33];
    const int nb = blockIdx.x * 32;
    const int kb = blockIdx.y * 32;
    const int tx = threadIdx.x;
    const int ty = threadIdx.y;

    #pragma unroll
    for (int i = ty; i < 32; i += 8)
        tile[i][tx] = w[(size_t)(kb + i) * N + nb + tx];
    __syncthreads();

    #pragma unroll
    for (int i = ty; i < 32; i += 8){
        const float v = tile[tx][i];
        Hh[(size_t)(nb + i) * C_ + kb + tx] = __float2half_rn(v);
    }
}

// ---------------------------------------------------------------------------
// Tensor-core GEMM, pure fp16 1-pass, 3-STAGE cp.async pipeline.
// 128x128 CTA tile, 8 warps (2m x 4n), occ 2, ldmatrix loads.
// MODE 1: A=X, B=Wa -> Q(scaled)/K single, V single transposed
// MODE 0: A=Y, B=Wp -> fp32 Cout (d_out)
// ---------------------------------------------------------------------------
constexpr int ROWB   = 80;
constexpr int MATB   = 128 * ROWB;   // 10240
constexpr int STAGEB = 2 * MATB;     // 20480 (A, B)
constexpr int GEMM_SMEM = 3 * STAGEB;// 61440

template<int MODE>
__global__ __launch_bounds__(256, 2)
void mma_gemm(const float* __restrict__ bias, float* __restrict__ Cout)
{
    extern __shared__ __align__(128) uint8_t smem[];

    const __half* Am = (MODE == 1) ? g_X  : g_Y;
    const __half* Bm = (MODE == 1) ? g_Wa : g_Wp;

    const int tid  = threadIdx.x;
    const int lane = tid & 31;
    const int warp = tid >> 5;
    const int wm   = warp & 1;
    const int wn   = warp >> 1;
    const int bc   = blockIdx.x;
    const int br   = blockIdx.y;

    const uint32_t sb = smem_u32(smem);

    auto load_stage = [&](int kt, int s){
        const uint32_t st = sb + (uint32_t)s * STAGEB;
        #pragma unroll
        for (int j = 0; j < 2; j++){
            const int ch  = tid + j*256;
            const int row = ch >> 2;
            const int cc  = ch & 3;
            const uint32_t so = (uint32_t)(row*ROWB + cc*16);
            const size_t ga = (size_t)(br*128 + row) * C_ + kt*32 + cc*8;
            const size_t gb = (size_t)(bc*128 + row) * C_ + kt*32 + cc*8;
            cpa16(st        + so, Am + ga);
            cpa16(st + MATB + so, Bm + gb);
        }
        asm volatile("cp.async.commit_group;");
    };

    float acc[4][4][4];
    #pragma unroll
    for (int i = 0; i < 4; i++)
        #pragma unroll
        for (int j = 0; j < 4; j++)
            #pragma unroll
            for (int q = 0; q < 4; q++) acc[i][j][q] = 0.f;

    constexpr int NK = C_ / 32;    // 24

    // 3-stage prologue: stages 0 and 1 in flight; wait for stage 0.
    load_stage(0, 0);
    load_stage(1, 1);
    asm volatile("cp.async.wait_group 1;");
    __syncthreads();

    const uint32_t offA = lm_offA(lane, ROWB) + (uint32_t)(wm*64)*ROWB;
    const uint32_t offB = lm_offB(lane, ROWB) + (uint32_t)(wn*32)*ROWB + MATB;

    for (int kt = 0; kt < NK; kt++){
        const int cur = kt % 3;
        // buffer (kt+2)%3 == (kt-1)%3: free since end-of-iter barrier of kt-1
        if (kt + 2 < NK) load_stage(kt + 2, (kt + 2) % 3);

        const uint32_t st = sb + (uint32_t)cur * STAGEB;

        #pragma unroll
        for (int kk = 0; kk < 2; kk++){
            uint32_t bf[4][2];
            #pragma unroll
            for (int jp = 0; jp < 2; jp++){
                const uint32_t ab = st + offB + (uint32_t)(jp*16)*ROWB + kk*32;
                ldsm4(bf[2*jp][0], bf[2*jp][1], bf[2*jp+1][0], bf[2*jp+1][1], ab);
            }
            #pragma unroll
            for (int i = 0; i < 4; i++){
                const uint32_t aa = st + offA + (uint32_t)(i*16)*ROWB + kk*32;
                uint32_t af[4];
                ldsm4(af[0], af[1], af[2], af[3], aa);
                #pragma unroll
                for (int j = 0; j < 4; j++) mma16816(acc[i][j], af, bf[j]);
            }
        }

        // ensure stage kt+1 complete before the next iteration reads it
        if (kt + 1 < NK){
            if (kt + 2 < NK) asm volatile("cp.async.wait_group 1;");
            else             asm volatile("cp.async.wait_group 0;");
        }
        __syncthreads();
    }

    const int r  = lane >> 2;
    const int c4 = lane & 3;

    // Epilogue
    #pragma unroll
    for (int j = 0; j < 4; j++){
        const int col = bc*128 + wn*32 + j*8 + c4*2;
        const float2 bv = *(const float2*)&bias[col];
        if (MODE == 0){
            #pragma unroll
            for (int i = 0; i < 4; i++){
                const int row0 = br*128 + wm*64 + i*16 + r;
                float2 v0 = make_float2(acc[i][j][0] + bv.x, acc[i][j][1] + bv.y);
                float2 v1 = make_float2(acc[i][j][2] + bv.x, acc[i][j][3] + bv.y);
                *(float2*)&Cout[(size_t)row0     * C_ + col] = v0;
                *(float2*)&Cout[(size_t)(row0+8) * C_ + col] = v1;
            }
        } else {
            const int which = col / C_;
            const int rem   = col - which * C_;
            const int hh = rem >> 6;
            const int dd = rem & 63;
            #pragma unroll
            for (int i = 0; i < 4; i++){
                const int row0 = br*128 + wm*64 + i*16 + r;
                const int b0i = row0 >> 10, t0i = row0 & 1023;
                const int row1 = row0 + 8;
                const int b1i = row1 >> 10, t1i = row1 & 1023;
                float v00 = acc[i][j][0] + bv.x, v01 = acc[i][j][1] + bv.y;
                float v10 = acc[i][j][2] + bv.x, v11 = acc[i][j][3] + bv.y;
                if (which == 0){ v00*=0.125f; v01*=0.125f; v10*=0.125f; v11*=0.125f; }
                const size_t o0 = ((size_t)(b0i*H_ + hh)*T_ + t0i)*HS_ + dd;
                const size_t o1 = ((size_t)(b1i*H_ + hh)*T_ + t1i)*HS_ + dd;
                if (which == 0){
                    *(uint32_t*)&g_Q[o0] = packhf(v00, v01);
                    *(uint32_t*)&g_Q[o1] = packhf(v10, v11);
                } else if (which == 1){
                    *(uint32_t*)&g_K[o0] = packhf(v00, v01);
                    *(uint32_t*)&g_K[o1] = packhf(v10, v11);
                } else {
                    // V transposed: [B,H,d,T]
                    const size_t vb0 = ((size_t)(b0i*H_ + hh)*HS_ + dd)*T_;
                    const size_t vb1 = ((size_t)(b1i*H_ + hh)*HS_ + dd)*T_;
                    g_V[vb0      + t0i] = __float2half_rn(v00);
                    g_V[vb0 + T_ + t0i] = __float2half_rn(v01);
                    g_V[vb1      + t1i] = __float2half_rn(v10);
                    g_V[vb1 + T_ + t1i] = __float2half_rn(v11);
                }
            }
        }
    }
}

// ---------------------------------------------------------------------------
// Tensor-core causal flash attention, pure fp16, 3-STAGE K/V pipeline.
// q-tile 128, k-tiles 64, occ 2, Q fragments register-cached (16 regs).
// smem: Q 18432 + 3 stages x (K 9216 + V 9216) = 73728 B.
// ---------------------------------------------------------------------------
constexpr int AQ_ROW = 144;
constexpr int AK_ROW = 144;
constexpr int AV_ROW = 144;
constexpr int A_MQ   = 128 * AQ_ROW;     // 18432
constexpr int A_MK   = 64  * AK_ROW;     // 9216
constexpr int A_MV   = 64  * AV_ROW;     // 9216
constexpr int A_VOFF = A_MK;
constexpr int A_STG  = A_MK + A_MV;      // 18432
constexpr int ATTN_SMEM = A_MQ + 3*A_STG;  // 73728

__global__ __launch_bounds__(256, 2)
void attn_tc()
{
    extern __shared__ __align__(128) uint8_t smx[];
    const uint32_t sb = smem_u32(smx);

    const int qt  = blockIdx.x;
    const int bh  = blockIdx.y;
    const int tid = threadIdx.x;
    const int lane = tid & 31;
    const int w    = tid >> 5;
    const int r    = lane >> 2;
    const int c4   = lane & 3;

    const size_t qoff = ((size_t)bh*T_ + qt*128) * HS_;
    #pragma unroll
    for (int j = 0; j < 4; j++){
        const int ch = tid + 256*j;
        const int row = ch >> 3, c = ch & 7;
        cpa16(sb + (uint32_t)(row*AQ_ROW + c*16),
              g_Q + qoff + (size_t)row*HS_ + c*8);
    }

    auto load_kv = [&](int kt2, int s){
        const uint32_t st = sb + A_MQ + (uint32_t)s * A_STG;
        const size_t koff = ((size_t)bh*T_ + kt2*64) * HS_;
        const size_t voff = (size_t)bh*HS_*T_ + kt2*64;
        #pragma unroll
        for (int j = 0; j < 2; j++){
            const int ch = tid + 256*j;
            const int row = ch >> 3, c = ch & 7;
            cpa16(st + (uint32_t)(row*AK_ROW + c*16),
                  g_K + koff + (size_t)row*HS_ + c*8);
            cpa16(st + A_VOFF + (uint32_t)(row*AV_ROW + c*16),
                  g_V + voff + (size_t)row*T_ + c*8);
        }
        asm volatile("cp.async.commit_group;");
    };

    const int nkt = 2*(qt + 1);

    // 3-stage prologue (group 0 also carries Q)
    load_kv(0, 0);
    if (nkt > 1){
        load_kv(1, 1);
        asm volatile("cp.async.wait_group 1;");
    } else {
        asm volatile("cp.async.wait_group 0;");
    }
    __syncthreads();

    float m0 = -1e30f, m1 = -1e30f, l0 = 0.f, l1 = 0.f;
    float o[8][4];
    #pragma unroll
    for (int j2 = 0; j2 < 8; j2++)
        #pragma unroll
        for (int q = 0; q < 4; q++) o[j2][q] = 0.f;

    const uint32_t offQ = lm_offA(lane, AQ_ROW) + (uint32_t)(w*16)*AQ_ROW;
    const uint32_t offK = lm_offB(lane, AK_ROW);
    const uint32_t offV = lm_offB(lane, AV_ROW);

    uint32_t q_r[4][4];   // loop-invariant Q fragments
    #pragma unroll
    for (int kk = 0; kk < 4; kk++){
        const uint32_t qa = sb + offQ + kk*32;
        ldsm4(q_r[kk][0], q_r[kk][1], q_r[kk][2], q_r[kk][3], qa);
    }

    for (int kt2 = 0; kt2 < nkt; kt2++){
        const int cur = kt2 % 3;
        if (kt2 + 2 < nkt) load_kv(kt2 + 2, (kt2 + 2) % 3);

        const uint32_t st = sb + A_MQ + (uint32_t)cur * A_STG;

        // ---- S = Q @ K^T (1-pass), 64 k-rows ----
        float s[8][4];
        #pragma unroll
        for (int j = 0; j < 8; j++){
            s[j][0] = s[j][1] = s[j][2] = s[j][3] = 0.f;
        }
        #pragma unroll
        for (int kk = 0; kk < 4; kk++){
            #pragma unroll
            for (int jq = 0; jq < 2; jq++){
                const uint32_t ka = st + offK
                                  + (uint32_t)(jq*32)*AK_ROW + kk*32;
                uint32_t kh[4][2];
                ldsm4(kh[0][0], kh[0][1], kh[1][0], kh[1][1], ka);
                ldsm4(kh[2][0], kh[2][1], kh[3][0], kh[3][1],
                      ka + (uint32_t)16*AK_ROW);
                mma16816(s[4*jq + 0], q_r[kk], kh[0]);
                mma16816(s[4*jq + 1], q_r[kk], kh[1]);
                mma16816(s[4*jq + 2], q_r[kk], kh[2]);
                mma16816(s[4*jq + 3], q_r[kk], kh[3]);
            }
        }

        // ---- causal mask ----
        if (kt2 >= 2*qt){
            const int base = (kt2 - 2*qt)*64;
            const int row0 = w*16 + r;
            #pragma unroll
            for (int j = 0; j < 8; j++){
                const int col0 = base + j*8 + c4*2;
                if (col0     > row0    ) s[j][0] = -1e30f;
                if (col0 + 1 > row0    ) s[j][1] = -1e30f;
                if (col0     > row0 + 8) s[j][2] = -1e30f;
                if (col0 + 1 > row0 + 8) s[j][3] = -1e30f;
            }
        }

        // ---- online softmax ----
        float rm0 = -1e30f, rm1 = -1e30f;
        #pragma unroll
        for (int j = 0; j < 8; j++){
            rm0 = fmaxf(rm0, fmaxf(s[j][0], s[j][1]));
            rm1 = fmaxf(rm1, fmaxf(s[j][2], s[j][3]));
        }
        rm0 = fmaxf(rm0, __shfl_xor_sync(0xffffffffu, rm0, 1));
        rm0 = fmaxf(rm0, __shfl_xor_sync(0xffffffffu, rm0, 2));
        rm1 = fmaxf(rm1, __shfl_xor_sync(0xffffffffu, rm1, 1));
        rm1 = fmaxf(rm1, __shfl_xor_sync(0xffffffffu, rm1, 2));
        const float mn0 = fmaxf(m0, rm0), mn1 = fmaxf(m1, rm1);
        const float a0 = __expf(m0 - mn0), a1 = __expf(m1 - mn1);
        m0 = mn0; m1 = mn1;
        float rs0 = 0.f, rs1 = 0.f;
        #pragma unroll
        for (int j = 0; j < 8; j++){
            s[j][0] = __expf(s[j][0] - mn0);
            s[j][1] = __expf(s[j][1] - mn0);
            s[j][2] = __expf(s[j][2] - mn1);
            s[j][3] = __expf(s[j][3] - mn1);
            rs0 += s[j][0] + s[j][1];
            rs1 += s[j][2] + s[j][3];
        }
        rs0 += __shfl_xor_sync(0xffffffffu, rs0, 1);
        rs0 += __shfl_xor_sync(0xffffffffu, rs0, 2);
        rs1 += __shfl_xor_sync(0xffffffffu, rs1, 1);
        rs1 += __shfl_xor_sync(0xffffffffu, rs1, 2);
        l0 = l0*a0 + rs0;
        l1 = l1*a1 + rs1;
        #pragma unroll
        for (int j2 = 0; j2 < 8; j2++){
            o[j2][0] *= a0; o[j2][1] *= a0;
            o[j2][2] *= a1; o[j2][3] *= a1;
        }

        // ---- O += P @ V (1-pass, P single fp16) ----
        #pragma unroll
        for (int kk = 0; kk < 4; kk++){
            uint32_t a_h[4];
            a_h[0] = packhf(s[2*kk  ][0], s[2*kk  ][1]);
            a_h[1] = packhf(s[2*kk  ][2], s[2*kk  ][3]);
            a_h[2] = packhf(s[2*kk+1][0], s[2*kk+1][1]);
            a_h[3] = packhf(s[2*kk+1][2], s[2*kk+1][3]);
            #pragma unroll
            for (int jq = 0; jq < 2; jq++){
                const uint32_t va = st + A_VOFF + offV
                                  + (uint32_t)(jq*32)*AV_ROW + kk*32;
                uint32_t vh[4][2];
                ldsm4(vh[0][0], vh[0][1], vh[1][0], vh[1][1], va);
                ldsm4(vh[2][0], vh[2][1], vh[3][0], vh[3][1],
                      va + (uint32_t)16*AV_ROW);
                mma16816(o[4*jq + 0], a_h, vh[0]);
                mma16816(o[4*jq + 1], a_h, vh[1]);
                mma16816(o[4*jq + 2], a_h, vh[2]);
                mma16816(o[4*jq + 3], a_h, vh[3]);
            }
        }

        if (kt2 + 1 < nkt){
            if (kt2 + 2 < nkt) asm volatile("cp.async.wait_group 1;");
            else               asm volatile("cp.async.wait_group 0;");
        }
        __syncthreads();
    }

    // ---- epilogue: write single fp16 Y [M][768] ----
    const float inv0 = 1.f / l0, inv1 = 1.f / l1;
    const int bq = bh / H_, hh = bh % H_;
    const int t0 = qt*128 + w*16 + r;
    #pragma unroll
    for (int j2 = 0; j2 < 8; j2++){
        const int cc = hh*64 + j2*8 + c4*2;
        const size_t r0 = (size_t)(bq*T_ + t0    )*C_ + cc;
        const size_t r1 = (size_t)(bq*T_ + t0 + 8)*C_ + cc;
        *(uint32_t*)&g_Y[r0] = packhf(o[j2][0]*inv0, o[j2][1]*inv0);
        *(uint32_t*)&g_Y[r1] = packhf(o[j2][2]*inv1, o[j2][3]*inv1);
    }
}

// ---------------------------------------------------------------------------
extern "C" void kernel_launch(void* const* d_in, const int* in_sizes, int n_in,
                              void* d_out, int out_size)
{
    const float* x      = (const float*)d_in[0];
    const float* w_attn = (const float*)d_in[1];
    const float* b_attn = (const float*)d_in[2];
    const float* w_proj = (const float*)d_in[3];
    const float* b_proj = (const float*)d_in[4];
    float* out = (float*)d_out;

    cudaFuncSetAttribute(mma_gemm<1>, cudaFuncAttributeMaxDynamicSharedMemorySize, GEMM_SMEM);
    cudaFuncSetAttribute(mma_gemm<0>, cudaFuncAttributeMaxDynamicSharedMemorySize, GEMM_SMEM);
    cudaFuncSetAttribute(attn_tc, cudaFuncAttributeMaxDynamicSharedMemorySize, ATTN_SMEM);

    convert_x<<<(M_*C_/4 + 255)/256, 256>>>(x);
    transpose_w<0><<<dim3(3*C_/32, C_/32), dim3(32, 8)>>>(w_attn);
    transpose_w<1><<<dim3(C_/32,   C_/32), dim3(32, 8)>>>(w_proj);

    mma_gemm<1><<<dim3(3*C_/128, M_/128), 256, GEMM_SMEM>>>(b_attn, nullptr);
    attn_tc<<<dim3(T_/128, B_*H_), 256, ATTN_SMEM>>>();
    mma_gemm<0><<<dim3(C_/128, M_/128), 256, GEMM_SMEM>>>(b_proj, out);
}

// round 16
// speedup vs baseline: 1.0428x; 1.0428x over previous
#include <cuda_runtime.h>
#include <cuda_fp16.h>
#include <cstdint>

// Problem constants
#define B_  8
#define T_  1024
#define C_  768
#define H_  12
#define HS_ 64
#define M_  8192   // B*T

// ---------------------------------------------------------------------------
// Device-global scratch (no runtime allocation allowed)
// X, Y, weights, Q (prescaled 0.125), K, V(transposed [B,H,hs,T]): single fp16.
// ---------------------------------------------------------------------------
__device__ __half g_X [(size_t)M_*C_];
__device__ __half g_Y [(size_t)M_*C_];
__device__ __half g_Wa[(size_t)3*C_*C_];
__device__ __half g_Wp[(size_t)C_*C_];

__device__ __half g_Q [B_*H_*T_*HS_];
__device__ __half g_K [B_*H_*T_*HS_];
__device__ __half g_V [B_*H_*T_*HS_];

// ---------------------------------------------------------------------------
// Helpers (portable PTX only — compiles for plain sm_103 target)
// ---------------------------------------------------------------------------
__device__ __forceinline__ uint32_t smem_u32(const void* p){
    return (uint32_t)__cvta_generic_to_shared(p);
}
__device__ __forceinline__ void cpa16(uint32_t d, const void* s){
    asm volatile("cp.async.cg.shared.global [%0], [%1], 16;" :: "r"(d), "l"(s));
}
__device__ __forceinline__ void ldsm4(uint32_t& r0, uint32_t& r1,
                                      uint32_t& r2, uint32_t& r3, uint32_t a){
    asm volatile("ldmatrix.sync.aligned.m8n8.x4.shared.b16 {%0,%1,%2,%3}, [%4];"
                 : "=r"(r0), "=r"(r1), "=r"(r2), "=r"(r3) : "r"(a));
}
__device__ __forceinline__ void mma16816(float acc[4], const uint32_t a[4],
                                         const uint32_t b[2]){
    asm volatile(
        "mma.sync.aligned.m16n8k16.row.col.f32.f16.f16.f32 "
        "{%0,%1,%2,%3}, {%4,%5,%6,%7}, {%8,%9}, {%0,%1,%2,%3};"
        : "+f"(acc[0]), "+f"(acc[1]), "+f"(acc[2]), "+f"(acc[3])
        : "r"(a[0]), "r"(a[1]), "r"(a[2]), "r"(a[3]), "r"(b[0]), "r"(b[1]));
}
__device__ __forceinline__ uint32_t packhf(float x, float y){
    __half2 t = __float22half2_rn(make_float2(x, y));
    return *(uint32_t*)&t;
}

// per-lane ldmatrix row-offset helpers (byte offsets within a tile):
__device__ __forceinline__ uint32_t lm_offA(int lane, int rowb){
    return (uint32_t)(((lane & 7) + ((lane >> 3) & 1)*8) * rowb + (lane >> 4)*16);
}
__device__ __forceinline__ uint32_t lm_offB(int lane, int rowb){
    return (uint32_t)(((lane & 7) + (lane >> 4)*8) * rowb + ((lane >> 3) & 1)*16);
}

// ---------------------------------------------------------------------------
// Pre-pass: convert x fp32 -> single fp16
// ---------------------------------------------------------------------------
__global__ void convert_x(const float* __restrict__ src)
{
    const int i = blockIdx.x * blockDim.x + threadIdx.x;   // float4 index
    const int n4 = (M_*C_) / 4;
    if (i >= n4) return;
    const float4 v = ((const float4*)src)[i];
    ((uint32_t*)g_X)[i*2    ] = packhf(v.x, v.y);
    ((uint32_t*)g_X)[i*2 + 1] = packhf(v.z, v.w);
}

// ---------------------------------------------------------------------------
// Pre-pass: transpose weights -> [N][768] single fp16 (K-major)
// ---------------------------------------------------------------------------
template<int WHICH>
__global__ void transpose_w(const float* __restrict__ w)
{
    constexpr int N = (WHICH == 0) ? 3*C_ : C_;
    __half* Hh = (WHICH == 0) ? g_Wa : g_Wp;

    __shared__ float tile[32][33];
    const int nb = blockIdx.x * 32;
    const int kb = blockIdx.y * 32;
    const int tx = threadIdx.x;
    const int ty = threadIdx.y;

    #pragma unroll
    for (int i = ty; i < 32; i += 8)
        tile[i][tx] = w[(size_t)(kb + i) * N + nb + tx];
    __syncthreads();

    #pragma unroll
    for (int i = ty; i < 32; i += 8){
        const float v = tile[tx][i];
        Hh[(size_t)(nb + i) * C_ + kb + tx] = __float2half_rn(v);
    }
}

// ---------------------------------------------------------------------------
// Tensor-core GEMM, pure fp16 1-pass, BK=64 (12 k-tiles, half the barriers).
// 128x128 CTA tile, 8 warps (2m x 4n), occ 2, ldmatrix loads, 2-stage pipe.
// MODE 1: A=X, B=Wa -> Q(scaled)/K single, V single transposed
// MODE 0: A=Y, B=Wp -> fp32 Cout (d_out)
// ---------------------------------------------------------------------------
constexpr int ROWB   = 144;          // 64 fp16 = 128 B + 16 pad
constexpr int MATB   = 128 * ROWB;   // 18432
constexpr int STAGEB = 2 * MATB;     // 36864 (A, B)
constexpr int GEMM_SMEM = 2 * STAGEB;// 73728

template<int MODE>
__global__ __launch_bounds__(256, 2)
void mma_gemm(const float* __restrict__ bias, float* __restrict__ Cout)
{
    extern __shared__ __align__(128) uint8_t smem[];

    const __half* Am = (MODE == 1) ? g_X  : g_Y;
    const __half* Bm = (MODE == 1) ? g_Wa : g_Wp;

    const int tid  = threadIdx.x;
    const int lane = tid & 31;
    const int warp = tid >> 5;
    const int wm   = warp & 1;
    const int wn   = warp >> 1;
    const int bc   = blockIdx.x;
    const int br   = blockIdx.y;

    const uint32_t sb = smem_u32(smem);

    auto load_stage = [&](int kt, int s){
        const uint32_t st = sb + (uint32_t)s * STAGEB;
        #pragma unroll
        for (int j = 0; j < 4; j++){
            const int ch  = tid + j*256;        // 0..1023
            const int row = ch >> 3;
            const int cc  = ch & 7;
            const uint32_t so = (uint32_t)(row*ROWB + cc*16);
            const size_t ga = (size_t)(br*128 + row) * C_ + kt*64 + cc*8;
            const size_t gb = (size_t)(bc*128 + row) * C_ + kt*64 + cc*8;
            cpa16(st        + so, Am + ga);
            cpa16(st + MATB + so, Bm + gb);
        }
        asm volatile("cp.async.commit_group;");
    };

    float acc[4][4][4];
    #pragma unroll
    for (int i = 0; i < 4; i++)
        #pragma unroll
        for (int j = 0; j < 4; j++)
            #pragma unroll
            for (int q = 0; q < 4; q++) acc[i][j][q] = 0.f;

    constexpr int NK = C_ / 64;    // 12

    load_stage(0, 0);
    asm volatile("cp.async.wait_group 0;");
    __syncthreads();

    const uint32_t offA = lm_offA(lane, ROWB) + (uint32_t)(wm*64)*ROWB;
    const uint32_t offB = lm_offB(lane, ROWB) + (uint32_t)(wn*32)*ROWB + MATB;

    for (int kt = 0; kt < NK; kt++){
        const int cur = kt & 1;
        if (kt + 1 < NK) load_stage(kt + 1, cur ^ 1);

        const uint32_t st = sb + (uint32_t)cur * STAGEB;

        #pragma unroll
        for (int kk = 0; kk < 4; kk++){
            uint32_t bf[4][2];
            #pragma unroll
            for (int jp = 0; jp < 2; jp++){
                const uint32_t ab = st + offB + (uint32_t)(jp*16)*ROWB + kk*32;
                ldsm4(bf[2*jp][0], bf[2*jp][1], bf[2*jp+1][0], bf[2*jp+1][1], ab);
            }
            #pragma unroll
            for (int i = 0; i < 4; i++){
                const uint32_t aa = st + offA + (uint32_t)(i*16)*ROWB + kk*32;
                uint32_t af[4];
                ldsm4(af[0], af[1], af[2], af[3], aa);
                #pragma unroll
                for (int j = 0; j < 4; j++) mma16816(acc[i][j], af, bf[j]);
            }
        }

        if (kt + 1 < NK) asm volatile("cp.async.wait_group 0;");
        __syncthreads();
    }

    const int r  = lane >> 2;
    const int c4 = lane & 3;

    // Epilogue
    #pragma unroll
    for (int j = 0; j < 4; j++){
        const int col = bc*128 + wn*32 + j*8 + c4*2;
        const float2 bv = *(const float2*)&bias[col];
        if (MODE == 0){
            #pragma unroll
            for (int i = 0; i < 4; i++){
                const int row0 = br*128 + wm*64 + i*16 + r;
                float2 v0 = make_float2(acc[i][j][0] + bv.x, acc[i][j][1] + bv.y);
                float2 v1 = make_float2(acc[i][j][2] + bv.x, acc[i][j][3] + bv.y);
                *(float2*)&Cout[(size_t)row0     * C_ + col] = v0;
                *(float2*)&Cout[(size_t)(row0+8) * C_ + col] = v1;
            }
        } else {
            const int which = col / C_;
            const int rem   = col - which * C_;
            const int hh = rem >> 6;
            const int dd = rem & 63;
            #pragma unroll
            for (int i = 0; i < 4; i++){
                const int row0 = br*128 + wm*64 + i*16 + r;
                const int b0i = row0 >> 10, t0i = row0 & 1023;
                const int row1 = row0 + 8;
                const int b1i = row1 >> 10, t1i = row1 & 1023;
                float v00 = acc[i][j][0] + bv.x, v01 = acc[i][j][1] + bv.y;
                float v10 = acc[i][j][2] + bv.x, v11 = acc[i][j][3] + bv.y;
                if (which == 0){ v00*=0.125f; v01*=0.125f; v10*=0.125f; v11*=0.125f; }
                const size_t o0 = ((size_t)(b0i*H_ + hh)*T_ + t0i)*HS_ + dd;
                const size_t o1 = ((size_t)(b1i*H_ + hh)*T_ + t1i)*HS_ + dd;
                if (which == 0){
                    *(uint32_t*)&g_Q[o0] = packhf(v00, v01);
                    *(uint32_t*)&g_Q[o1] = packhf(v10, v11);
                } else if (which == 1){
                    *(uint32_t*)&g_K[o0] = packhf(v00, v01);
                    *(uint32_t*)&g_K[o1] = packhf(v10, v11);
                } else {
                    // V transposed: [B,H,d,T]
                    const size_t vb0 = ((size_t)(b0i*H_ + hh)*HS_ + dd)*T_;
                    const size_t vb1 = ((size_t)(b1i*H_ + hh)*HS_ + dd)*T_;
                    g_V[vb0      + t0i] = __float2half_rn(v00);
                    g_V[vb0 + T_ + t0i] = __float2half_rn(v01);
                    g_V[vb1      + t1i] = __float2half_rn(v10);
                    g_V[vb1 + T_ + t1i] = __float2half_rn(v11);
                }
            }
        }
    }
}

// ---------------------------------------------------------------------------
// Tensor-core causal flash attention, pure fp16 (1-pass S, 1-pass PV) —
// exact R14 best config: q-tile 128, k-tiles 64, 2-stage, occ 2, Q in regs.
// smem: Q 18432 + 2 stages x (K 9216 + V 9216) = 55296 B.
// ---------------------------------------------------------------------------
constexpr int AQ_ROW = 144;
constexpr int AK_ROW = 144;
constexpr int AV_ROW = 144;
constexpr int A_MQ   = 128 * AQ_ROW;     // 18432
constexpr int A_MK   = 64  * AK_ROW;     // 9216
constexpr int A_MV   = 64  * AV_ROW;     // 9216
constexpr int A_VOFF = A_MK;
constexpr int A_STG  = A_MK + A_MV;      // 18432
constexpr int ATTN_SMEM = A_MQ + 2*A_STG;  // 55296

__global__ __launch_bounds__(256, 2)
void attn_tc()
{
    extern __shared__ __align__(128) uint8_t smx[];
    const uint32_t sb = smem_u32(smx);

    const int qt  = blockIdx.x;
    const int bh  = blockIdx.y;
    const int tid = threadIdx.x;
    const int lane = tid & 31;
    const int w    = tid >> 5;
    const int r    = lane >> 2;
    const int c4   = lane & 3;

    const size_t qoff = ((size_t)bh*T_ + qt*128) * HS_;
    #pragma unroll
    for (int j = 0; j < 4; j++){
        const int ch = tid + 256*j;
        const int row = ch >> 3, c = ch & 7;
        cpa16(sb + (uint32_t)(row*AQ_ROW + c*16),
              g_Q + qoff + (size_t)row*HS_ + c*8);
    }

    auto load_kv = [&](int kt2, int s){
        const uint32_t st = sb + A_MQ + (uint32_t)s * A_STG;
        const size_t koff = ((size_t)bh*T_ + kt2*64) * HS_;
        const size_t voff = (size_t)bh*HS_*T_ + kt2*64;
        #pragma unroll
        for (int j = 0; j < 2; j++){
            const int ch = tid + 256*j;
            const int row = ch >> 3, c = ch & 7;
            cpa16(st + (uint32_t)(row*AK_ROW + c*16),
                  g_K + koff + (size_t)row*HS_ + c*8);
            cpa16(st + A_VOFF + (uint32_t)(row*AV_ROW + c*16),
                  g_V + voff + (size_t)row*T_ + c*8);
        }
        asm volatile("cp.async.commit_group;");
    };

    load_kv(0, 0);

    float m0 = -1e30f, m1 = -1e30f, l0 = 0.f, l1 = 0.f;
    float o[8][4];
    #pragma unroll
    for (int j2 = 0; j2 < 8; j2++)
        #pragma unroll
        for (int q = 0; q < 4; q++) o[j2][q] = 0.f;

    const uint32_t offQ = lm_offA(lane, AQ_ROW) + (uint32_t)(w*16)*AQ_ROW;
    const uint32_t offK = lm_offB(lane, AK_ROW);
    const uint32_t offV = lm_offB(lane, AV_ROW);

    uint32_t q_r[4][4];   // loop-invariant Q fragments

    const int nkt = 2*(qt + 1);

    for (int kt2 = 0; kt2 < nkt; kt2++){
        if (kt2 + 1 < nkt){
            load_kv(kt2 + 1, (kt2 + 1) & 1);
            asm volatile("cp.async.wait_group 1;");
        } else {
            asm volatile("cp.async.wait_group 0;");
        }
        __syncthreads();

        if (kt2 == 0){
            #pragma unroll
            for (int kk = 0; kk < 4; kk++){
                const uint32_t qa = sb + offQ + kk*32;
                ldsm4(q_r[kk][0], q_r[kk][1], q_r[kk][2], q_r[kk][3], qa);
            }
        }

        const uint32_t st = sb + A_MQ + (uint32_t)(kt2 & 1) * A_STG;

        // ---- S = Q @ K^T (1-pass), 64 k-rows ----
        float s[8][4];
        #pragma unroll
        for (int j = 0; j < 8; j++){
            s[j][0] = s[j][1] = s[j][2] = s[j][3] = 0.f;
        }
        #pragma unroll
        for (int kk = 0; kk < 4; kk++){
            #pragma unroll
            for (int jq = 0; jq < 2; jq++){
                const uint32_t ka = st + offK
                                  + (uint32_t)(jq*32)*AK_ROW + kk*32;
                uint32_t kh[4][2];
                ldsm4(kh[0][0], kh[0][1], kh[1][0], kh[1][1], ka);
                ldsm4(kh[2][0], kh[2][1], kh[3][0], kh[3][1],
                      ka + (uint32_t)16*AK_ROW);
                mma16816(s[4*jq + 0], q_r[kk], kh[0]);
                mma16816(s[4*jq + 1], q_r[kk], kh[1]);
                mma16816(s[4*jq + 2], q_r[kk], kh[2]);
                mma16816(s[4*jq + 3], q_r[kk], kh[3]);
            }
        }

        // ---- causal mask ----
        if (kt2 >= 2*qt){
            const int base = (kt2 - 2*qt)*64;
            const int row0 = w*16 + r;
            #pragma unroll
            for (int j = 0; j < 8; j++){
                const int col0 = base + j*8 + c4*2;
                if (col0     > row0    ) s[j][0] = -1e30f;
                if (col0 + 1 > row0    ) s[j][1] = -1e30f;
                if (col0     > row0 + 8) s[j][2] = -1e30f;
                if (col0 + 1 > row0 + 8) s[j][3] = -1e30f;
            }
        }

        // ---- online softmax ----
        float rm0 = -1e30f, rm1 = -1e30f;
        #pragma unroll
        for (int j = 0; j < 8; j++){
            rm0 = fmaxf(rm0, fmaxf(s[j][0], s[j][1]));
            rm1 = fmaxf(rm1, fmaxf(s[j][2], s[j][3]));
        }
        rm0 = fmaxf(rm0, __shfl_xor_sync(0xffffffffu, rm0, 1));
        rm0 = fmaxf(rm0, __shfl_xor_sync(0xffffffffu, rm0, 2));
        rm1 = fmaxf(rm1, __shfl_xor_sync(0xffffffffu, rm1, 1));
        rm1 = fmaxf(rm1, __shfl_xor_sync(0xffffffffu, rm1, 2));
        const float mn0 = fmaxf(m0, rm0), mn1 = fmaxf(m1, rm1);
        const float a0 = __expf(m0 - mn0), a1 = __expf(m1 - mn1);
        m0 = mn0; m1 = mn1;
        float rs0 = 0.f, rs1 = 0.f;
        #pragma unroll
        for (int j = 0; j < 8; j++){
            s[j][0] = __expf(s[j][0] - mn0);
            s[j][1] = __expf(s[j][1] - mn0);
            s[j][2] = __expf(s[j][2] - mn1);
            s[j][3] = __expf(s[j][3] - mn1);
            rs0 += s[j][0] + s[j][1];
            rs1 += s[j][2] + s[j][3];
        }
        rs0 += __shfl_xor_sync(0xffffffffu, rs0, 1);
        rs0 += __shfl_xor_sync(0xffffffffu, rs0, 2);
        rs1 += __shfl_xor_sync(0xffffffffu, rs1, 1);
        rs1 += __shfl_xor_sync(0xffffffffu, rs1, 2);
        l0 = l0*a0 + rs0;
        l1 = l1*a1 + rs1;
        #pragma unroll
        for (int j2 = 0; j2 < 8; j2++){
            o[j2][0] *= a0; o[j2][1] *= a0;
            o[j2][2] *= a1; o[j2][3] *= a1;
        }

        // ---- O += P @ V (1-pass, P single fp16) ----
        #pragma unroll
        for (int kk = 0; kk < 4; kk++){
            uint32_t a_h[4];
            a_h[0] = packhf(s[2*kk  ][0], s[2*kk  ][1]);
            a_h[1] = packhf(s[2*kk  ][2], s[2*kk  ][3]);
            a_h[2] = packhf(s[2*kk+1][0], s[2*kk+1][1]);
            a_h[3] = packhf(s[2*kk+1][2], s[2*kk+1][3]);
            #pragma unroll
            for (int jq = 0; jq < 2; jq++){
                const uint32_t va = st + A_VOFF + offV
                                  + (uint32_t)(jq*32)*AV_ROW + kk*32;
                uint32_t vh[4][2];
                ldsm4(vh[0][0], vh[0][1], vh[1][0], vh[1][1], va);
                ldsm4(vh[2][0], vh[2][1], vh[3][0], vh[3][1],
                      va + (uint32_t)16*AV_ROW);
                mma16816(o[4*jq + 0], a_h, vh[0]);
                mma16816(o[4*jq + 1], a_h, vh[1]);
                mma16816(o[4*jq + 2], a_h, vh[2]);
                mma16816(o[4*jq + 3], a_h, vh[3]);
            }
        }
        __syncthreads();
    }

    // ---- epilogue: write single fp16 Y [M][768] ----
    const float inv0 = 1.f / l0, inv1 = 1.f / l1;
    const int bq = bh / H_, hh = bh % H_;
    const int t0 = qt*128 + w*16 + r;
    #pragma unroll
    for (int j2 = 0; j2 < 8; j2++){
        const int cc = hh*64 + j2*8 + c4*2;
        const size_t r0 = (size_t)(bq*T_ + t0    )*C_ + cc;
        const size_t r1 = (size_t)(bq*T_ + t0 + 8)*C_ + cc;
        *(uint32_t*)&g_Y[r0] = packhf(o[j2][0]*inv0, o[j2][1]*inv0);
        *(uint32_t*)&g_Y[r1] = packhf(o[j2][2]*inv1, o[j2][3]*inv1);
    }
}

// ---------------------------------------------------------------------------
extern "C" void kernel_launch(void* const* d_in, const int* in_sizes, int n_in,
                              void* d_out, int out_size)
{
    const float* x      = (const float*)d_in[0];
    const float* w_attn = (const float*)d_in[1];
    const float* b_attn = (const float*)d_in[2];
    const float* w_proj = (const float*)d_in[3];
    const float* b_proj = (const float*)d_in[4];
    float* out = (float*)d_out;

    cudaFuncSetAttribute(mma_gemm<1>, cudaFuncAttributeMaxDynamicSharedMemorySize, GEMM_SMEM);
    cudaFuncSetAttribute(mma_gemm<0>, cudaFuncAttributeMaxDynamicSharedMemorySize, GEMM_SMEM);
    cudaFuncSetAttribute(attn_tc, cudaFuncAttributeMaxDynamicSharedMemorySize, ATTN_SMEM);

    convert_x<<<(M_*C_/4 + 255)/256, 256>>>(x);
    transpose_w<0><<<dim3(3*C_/32, C_/32), dim3(32, 8)>>>(w_attn);
    transpose_w<1><<<dim3(C_/32,   C_/32), dim3(32, 8)>>>(w_proj);

    mma_gemm<1><<<dim3(3*C_/128, M_/128), 256, GEMM_SMEM>>>(b_attn, nullptr);
    attn_tc<<<dim3(T_/128, B_*H_), 256, ATTN_SMEM>>>();
    mma_gemm<0><<<dim3(C_/128, M_/128), 256, GEMM_SMEM>>>(b_proj, out);
}

// round 17
// speedup vs baseline: 1.0940x; 1.0492x over previous
#include <cuda_runtime.h>
#include <cuda_fp16.h>
#include <cstdint>

// Problem constants
#define B_  8
#define T_  1024
#define C_  768
#define H_  12
#define HS_ 64
#define M_  8192   // B*T

// ---------------------------------------------------------------------------
// Device-global scratch (no runtime allocation allowed)
// X, Y, weights, Q (prescaled 0.125), K, V(transposed [B,H,hs,T]): single fp16.
// ---------------------------------------------------------------------------
__device__ __half g_X [(size_t)M_*C_];
__device__ __half g_Y [(size_t)M_*C_];
__device__ __half g_Wa[(size_t)3*C_*C_];
__device__ __half g_Wp[(size_t)C_*C_];

__device__ __half g_Q [B_*H_*T_*HS_];
__device__ __half g_K [B_*H_*T_*HS_];
__device__ __half g_V [B_*H_*T_*HS_];

// ---------------------------------------------------------------------------
// Helpers (portable PTX only — compiles for plain sm_103 target)
// ---------------------------------------------------------------------------
__device__ __forceinline__ uint32_t smem_u32(const void* p){
    return (uint32_t)__cvta_generic_to_shared(p);
}
__device__ __forceinline__ void cpa16(uint32_t d, const void* s){
    asm volatile("cp.async.cg.shared.global [%0], [%1], 16;" :: "r"(d), "l"(s));
}
__device__ __forceinline__ void ldsm4(uint32_t& r0, uint32_t& r1,
                                      uint32_t& r2, uint32_t& r3, uint32_t a){
    asm volatile("ldmatrix.sync.aligned.m8n8.x4.shared.b16 {%0,%1,%2,%3}, [%4];"
                 : "=r"(r0), "=r"(r1), "=r"(r2), "=r"(r3) : "r"(a));
}
__device__ __forceinline__ void mma16816(float acc[4], const uint32_t a[4],
                                         const uint32_t b[2]){
    asm volatile(
        "mma.sync.aligned.m16n8k16.row.col.f32.f16.f16.f32 "
        "{%0,%1,%2,%3}, {%4,%5,%6,%7}, {%8,%9}, {%0,%1,%2,%3};"
        : "+f"(acc[0]), "+f"(acc[1]), "+f"(acc[2]), "+f"(acc[3])
        : "r"(a[0]), "r"(a[1]), "r"(a[2]), "r"(a[3]), "r"(b[0]), "r"(b[1]));
}
__device__ __forceinline__ uint32_t packhf(float x, float y){
    __half2 t = __float22half2_rn(make_float2(x, y));
    return *(uint32_t*)&t;
}

// per-lane ldmatrix row-offset helpers (byte offsets within a tile):
__device__ __forceinline__ uint32_t lm_offA(int lane, int rowb){
    return (uint32_t)(((lane & 7) + ((lane >> 3) & 1)*8) * rowb + (lane >> 4)*16);
}
__device__ __forceinline__ uint32_t lm_offB(int lane, int rowb){
    return (uint32_t)(((lane & 7) + (lane >> 4)*8) * rowb + ((lane >> 3) & 1)*16);
}

// ---------------------------------------------------------------------------
// Fused pre-pass: one launch does x->fp16 + both weight transposes.
// Block ranges: [0,6144) convert_x; [6144,7872) wa; [7872,8448) wp.
// ---------------------------------------------------------------------------
constexpr int PB_X  = (M_*C_/4) / 256;          // 6144
constexpr int PB_WA = (3*C_/32) * (C_/32);      // 1728
constexpr int PB_WP = (C_/32) * (C_/32);        // 576
constexpr int PB_TOT = PB_X + PB_WA + PB_WP;    // 8448

__global__ void prepass(const float* __restrict__ x,
                        const float* __restrict__ wa,
                        const float* __restrict__ wp)
{
    const int b = blockIdx.x;
    if (b < PB_X){
        const int i = b * 256 + threadIdx.x;     // float4 index
        const float4 v = ((const float4*)x)[i];
        ((uint32_t*)g_X)[i*2    ] = packhf(v.x, v.y);
        ((uint32_t*)g_X)[i*2 + 1] = packhf(v.z, v.w);
        return;
    }
    // transpose path: 256 threads = 32(tx) x 8(ty)
    __shared__ float tile[32][33];
    const int tx = threadIdx.x & 31;
    const int ty = threadIdx.x >> 5;

    const float* w; __half* Hh; int N, nb, kb;
    if (b < PB_X + PB_WA){
        const int bb = b - PB_X;
        w = wa; Hh = g_Wa; N = 3*C_;
        nb = (bb % (3*C_/32)) * 32;
        kb = (bb / (3*C_/32)) * 32;
    } else {
        const int bb = b - PB_X - PB_WA;
        w = wp; Hh = g_Wp; N = C_;
        nb = (bb % (C_/32)) * 32;
        kb = (bb / (C_/32)) * 32;
    }

    #pragma unroll
    for (int i = ty; i < 32; i += 8)
        tile[i][tx] = w[(size_t)(kb + i) * N + nb + tx];
    __syncthreads();

    #pragma unroll
    for (int i = ty; i < 32; i += 8)
        Hh[(size_t)(nb + i) * C_ + kb + tx] = __float2half_rn(tile[tx][i]);
}

// ---------------------------------------------------------------------------
// Tensor-core GEMM — exact R16 best: fp16 1-pass, BK=64, 2-stage, occ 2.
// MODE 1: A=X, B=Wa -> Q(scaled)/K single, V single transposed
// MODE 0: A=Y, B=Wp -> fp32 Cout (d_out)
// ---------------------------------------------------------------------------
constexpr int ROWB   = 144;          // 64 fp16 = 128 B + 16 pad
constexpr int MATB   = 128 * ROWB;   // 18432
constexpr int STAGEB = 2 * MATB;     // 36864 (A, B)
constexpr int GEMM_SMEM = 2 * STAGEB;// 73728

template<int MODE>
__global__ __launch_bounds__(256, 2)
void mma_gemm(const float* __restrict__ bias, float* __restrict__ Cout)
{
    extern __shared__ __align__(128) uint8_t smem[];

    const __half* Am = (MODE == 1) ? g_X  : g_Y;
    const __half* Bm = (MODE == 1) ? g_Wa : g_Wp;

    const int tid  = threadIdx.x;
    const int lane = tid & 31;
    const int warp = tid >> 5;
    const int wm   = warp & 1;
    const int wn   = warp >> 1;
    const int bc   = blockIdx.x;
    const int br   = blockIdx.y;

    const uint32_t sb = smem_u32(smem);

    auto load_stage = [&](int kt, int s){
        const uint32_t st = sb + (uint32_t)s * STAGEB;
        #pragma unroll
        for (int j = 0; j < 4; j++){
            const int ch  = tid + j*256;        // 0..1023
            const int row = ch >> 3;
            const int cc  = ch & 7;
            const uint32_t so = (uint32_t)(row*ROWB + cc*16);
            const size_t ga = (size_t)(br*128 + row) * C_ + kt*64 + cc*8;
            const size_t gb = (size_t)(bc*128 + row) * C_ + kt*64 + cc*8;
            cpa16(st        + so, Am + ga);
            cpa16(st + MATB + so, Bm + gb);
        }
        asm volatile("cp.async.commit_group;");
    };

    float acc[4][4][4];
    #pragma unroll
    for (int i = 0; i < 4; i++)
        #pragma unroll
        for (int j = 0; j < 4; j++)
            #pragma unroll
            for (int q = 0; q < 4; q++) acc[i][j][q] = 0.f;

    constexpr int NK = C_ / 64;    // 12

    load_stage(0, 0);
    asm volatile("cp.async.wait_group 0;");
    __syncthreads();

    const uint32_t offA = lm_offA(lane, ROWB) + (uint32_t)(wm*64)*ROWB;
    const uint32_t offB = lm_offB(lane, ROWB) + (uint32_t)(wn*32)*ROWB + MATB;

    for (int kt = 0; kt < NK; kt++){
        const int cur = kt & 1;
        if (kt + 1 < NK) load_stage(kt + 1, cur ^ 1);

        const uint32_t st = sb + (uint32_t)cur * STAGEB;

        #pragma unroll
        for (int kk = 0; kk < 4; kk++){
            uint32_t bf[4][2];
            #pragma unroll
            for (int jp = 0; jp < 2; jp++){
                const uint32_t ab = st + offB + (uint32_t)(jp*16)*ROWB + kk*32;
                ldsm4(bf[2*jp][0], bf[2*jp][1], bf[2*jp+1][0], bf[2*jp+1][1], ab);
            }
            #pragma unroll
            for (int i = 0; i < 4; i++){
                const uint32_t aa = st + offA + (uint32_t)(i*16)*ROWB + kk*32;
                uint32_t af[4];
                ldsm4(af[0], af[1], af[2], af[3], aa);
                #pragma unroll
                for (int j = 0; j < 4; j++) mma16816(acc[i][j], af, bf[j]);
            }
        }

        if (kt + 1 < NK) asm volatile("cp.async.wait_group 0;");
        __syncthreads();
    }

    const int r  = lane >> 2;
    const int c4 = lane & 3;

    // Epilogue
    #pragma unroll
    for (int j = 0; j < 4; j++){
        const int col = bc*128 + wn*32 + j*8 + c4*2;
        const float2 bv = *(const float2*)&bias[col];
        if (MODE == 0){
            #pragma unroll
            for (int i = 0; i < 4; i++){
                const int row0 = br*128 + wm*64 + i*16 + r;
                float2 v0 = make_float2(acc[i][j][0] + bv.x, acc[i][j][1] + bv.y);
                float2 v1 = make_float2(acc[i][j][2] + bv.x, acc[i][j][3] + bv.y);
                *(float2*)&Cout[(size_t)row0     * C_ + col] = v0;
                *(float2*)&Cout[(size_t)(row0+8) * C_ + col] = v1;
            }
        } else {
            const int which = col / C_;
            const int rem   = col - which * C_;
            const int hh = rem >> 6;
            const int dd = rem & 63;
            #pragma unroll
            for (int i = 0; i < 4; i++){
                const int row0 = br*128 + wm*64 + i*16 + r;
                const int b0i = row0 >> 10, t0i = row0 & 1023;
                const int row1 = row0 + 8;
                const int b1i = row1 >> 10, t1i = row1 & 1023;
                float v00 = acc[i][j][0] + bv.x, v01 = acc[i][j][1] + bv.y;
                float v10 = acc[i][j][2] + bv.x, v11 = acc[i][j][3] + bv.y;
                if (which == 0){ v00*=0.125f; v01*=0.125f; v10*=0.125f; v11*=0.125f; }
                const size_t o0 = ((size_t)(b0i*H_ + hh)*T_ + t0i)*HS_ + dd;
                const size_t o1 = ((size_t)(b1i*H_ + hh)*T_ + t1i)*HS_ + dd;
                if (which == 0){
                    *(uint32_t*)&g_Q[o0] = packhf(v00, v01);
                    *(uint32_t*)&g_Q[o1] = packhf(v10, v11);
                } else if (which == 1){
                    *(uint32_t*)&g_K[o0] = packhf(v00, v01);
                    *(uint32_t*)&g_K[o1] = packhf(v10, v11);
                } else {
                    // V transposed: [B,H,d,T]
                    const size_t vb0 = ((size_t)(b0i*H_ + hh)*HS_ + dd)*T_;
                    const size_t vb1 = ((size_t)(b1i*H_ + hh)*HS_ + dd)*T_;
                    g_V[vb0      + t0i] = __float2half_rn(v00);
                    g_V[vb0 + T_ + t0i] = __float2half_rn(v01);
                    g_V[vb1      + t1i] = __float2half_rn(v10);
                    g_V[vb1 + T_ + t1i] = __float2half_rn(v11);
                }
            }
        }
    }
}

// ---------------------------------------------------------------------------
// Tensor-core causal flash attention, pure fp16, PAIRED-BARRIER 4-buffer ring.
// q-tile 128, k-tiles 64, occ 2, Q fragments register-cached.
// One wait+barrier per PAIR of k-tiles.
// smem: Q 18432 + 4 stages x 18432 = 92160 B -> 2 CTAs/SM.
// ---------------------------------------------------------------------------
constexpr int AQ_ROW = 144;
constexpr int AK_ROW = 144;
constexpr int AV_ROW = 144;
constexpr int A_MQ   = 128 * AQ_ROW;     // 18432
constexpr int A_MK   = 64  * AK_ROW;     // 9216
constexpr int A_MV   = 64  * AV_ROW;     // 9216
constexpr int A_VOFF = A_MK;
constexpr int A_STG  = A_MK + A_MV;      // 18432
constexpr int ATTN_SMEM = A_MQ + 4*A_STG;  // 92160

__global__ __launch_bounds__(256, 2)
void attn_tc()
{
    extern __shared__ __align__(128) uint8_t smx[];
    const uint32_t sb = smem_u32(smx);

    const int qt  = blockIdx.x;
    const int bh  = blockIdx.y;
    const int tid = threadIdx.x;
    const int lane = tid & 31;
    const int w    = tid >> 5;
    const int r    = lane >> 2;
    const int c4   = lane & 3;

    const size_t qoff = ((size_t)bh*T_ + qt*128) * HS_;
    #pragma unroll
    for (int j = 0; j < 4; j++){
        const int ch = tid + 256*j;
        const int row = ch >> 3, c = ch & 7;
        cpa16(sb + (uint32_t)(row*AQ_ROW + c*16),
              g_Q + qoff + (size_t)row*HS_ + c*8);
    }

    auto load_kv = [&](int kt2){
        const uint32_t st = sb + A_MQ + (uint32_t)(kt2 & 3) * A_STG;
        const size_t koff = ((size_t)bh*T_ + kt2*64) * HS_;
        const size_t voff = (size_t)bh*HS_*T_ + kt2*64;
        #pragma unroll
        for (int j = 0; j < 2; j++){
            const int ch = tid + 256*j;
            const int row = ch >> 3, c = ch & 7;
            cpa16(st + (uint32_t)(row*AK_ROW + c*16),
                  g_K + koff + (size_t)row*HS_ + c*8);
            cpa16(st + A_VOFF + (uint32_t)(row*AV_ROW + c*16),
                  g_V + voff + (size_t)row*T_ + c*8);
        }
        asm volatile("cp.async.commit_group;");
    };

    float m0 = -1e30f, m1 = -1e30f, l0 = 0.f, l1 = 0.f;
    float o[8][4];
    #pragma unroll
    for (int j2 = 0; j2 < 8; j2++)
        #pragma unroll
        for (int q = 0; q < 4; q++) o[j2][q] = 0.f;

    const uint32_t offQ = lm_offA(lane, AQ_ROW) + (uint32_t)(w*16)*AQ_ROW;
    const uint32_t offK = lm_offB(lane, AK_ROW);
    const uint32_t offV = lm_offB(lane, AV_ROW);

    uint32_t q_r[4][4];

    // per-tile compute (S -> mask -> online softmax -> PV)
    auto compute_tile = [&](int kt2){
        const uint32_t st = sb + A_MQ + (uint32_t)(kt2 & 3) * A_STG;

        float s[8][4];
        #pragma unroll
        for (int j = 0; j < 8; j++){
            s[j][0] = s[j][1] = s[j][2] = s[j][3] = 0.f;
        }
        #pragma unroll
        for (int kk = 0; kk < 4; kk++){
            #pragma unroll
            for (int jq = 0; jq < 2; jq++){
                const uint32_t ka = st + offK
                                  + (uint32_t)(jq*32)*AK_ROW + kk*32;
                uint32_t kh[4][2];
                ldsm4(kh[0][0], kh[0][1], kh[1][0], kh[1][1], ka);
                ldsm4(kh[2][0], kh[2][1], kh[3][0], kh[3][1],
                      ka + (uint32_t)16*AK_ROW);
                mma16816(s[4*jq + 0], q_r[kk], kh[0]);
                mma16816(s[4*jq + 1], q_r[kk], kh[1]);
                mma16816(s[4*jq + 2], q_r[kk], kh[2]);
                mma16816(s[4*jq + 3], q_r[kk], kh[3]);
            }
        }

        if (kt2 >= 2*qt){
            const int base = (kt2 - 2*qt)*64;
            const int row0 = w*16 + r;
            #pragma unroll
            for (int j = 0; j < 8; j++){
                const int col0 = base + j*8 + c4*2;
                if (col0     > row0    ) s[j][0] = -1e30f;
                if (col0 + 1 > row0    ) s[j][1] = -1e30f;
                if (col0     > row0 + 8) s[j][2] = -1e30f;
                if (col0 + 1 > row0 + 8) s[j][3] = -1e30f;
            }
        }

        float rm0 = -1e30f, rm1 = -1e30f;
        #pragma unroll
        for (int j = 0; j < 8; j++){
            rm0 = fmaxf(rm0, fmaxf(s[j][0], s[j][1]));
            rm1 = fmaxf(rm1, fmaxf(s[j][2], s[j][3]));
        }
        rm0 = fmaxf(rm0, __shfl_xor_sync(0xffffffffu, rm0, 1));
        rm0 = fmaxf(rm0, __shfl_xor_sync(0xffffffffu, rm0, 2));
        rm1 = fmaxf(rm1, __shfl_xor_sync(0xffffffffu, rm1, 1));
        rm1 = fmaxf(rm1, __shfl_xor_sync(0xffffffffu, rm1, 2));
        const float mn0 = fmaxf(m0, rm0), mn1 = fmaxf(m1, rm1);
        const float a0 = __expf(m0 - mn0), a1 = __expf(m1 - mn1);
        m0 = mn0; m1 = mn1;
        float rs0 = 0.f, rs1 = 0.f;
        #pragma unroll
        for (int j = 0; j < 8; j++){
            s[j][0] = __expf(s[j][0] - mn0);
            s[j][1] = __expf(s[j][1] - mn0);
            s[j][2] = __expf(s[j][2] - mn1);
            s[j][3] = __expf(s[j][3] - mn1);
            rs0 += s[j][0] + s[j][1];
            rs1 += s[j][2] + s[j][3];
        }
        rs0 += __shfl_xor_sync(0xffffffffu, rs0, 1);
        rs0 += __shfl_xor_sync(0xffffffffu, rs0, 2);
        rs1 += __shfl_xor_sync(0xffffffffu, rs1, 1);
        rs1 += __shfl_xor_sync(0xffffffffu, rs1, 2);
        l0 = l0*a0 + rs0;
        l1 = l1*a1 + rs1;
        #pragma unroll
        for (int j2 = 0; j2 < 8; j2++){
            o[j2][0] *= a0; o[j2][1] *= a0;
            o[j2][2] *= a1; o[j2][3] *= a1;
        }

        #pragma unroll
        for (int kk = 0; kk < 4; kk++){
            uint32_t a_h[4];
            a_h[0] = packhf(s[2*kk  ][0], s[2*kk  ][1]);
            a_h[1] = packhf(s[2*kk  ][2], s[2*kk  ][3]);
            a_h[2] = packhf(s[2*kk+1][0], s[2*kk+1][1]);
            a_h[3] = packhf(s[2*kk+1][2], s[2*kk+1][3]);
            #pragma unroll
            for (int jq = 0; jq < 2; jq++){
                const uint32_t va = st + A_VOFF + offV
                                  + (uint32_t)(jq*32)*AV_ROW + kk*32;
                uint32_t vh[4][2];
                ldsm4(vh[0][0], vh[0][1], vh[1][0], vh[1][1], va);
                ldsm4(vh[2][0], vh[2][1], vh[3][0], vh[3][1],
                      va + (uint32_t)16*AV_ROW);
                mma16816(o[4*jq + 0], a_h, vh[0]);
                mma16816(o[4*jq + 1], a_h, vh[1]);
                mma16816(o[4*jq + 2], a_h, vh[2]);
                mma16816(o[4*jq + 3], a_h, vh[3]);
            }
        }
    };

    const int nkt = 2*(qt + 1);      // always even
    const int npair = nkt >> 1;

    // prologue: first pair in flight (group 0 also carries Q)
    load_kv(0);
    load_kv(1);

    for (int p = 0; p < npair; p++){
        asm volatile("cp.async.wait_group 0;");
        __syncthreads();
        // All warps have passed the end of pair p-1 compute here, so issuing
        // loads into pair p-1's buffers (= (2p+2..3) & 3) is safe.
        if (p == 0){
            #pragma unroll
            for (int kk = 0; kk < 4; kk++){
                const uint32_t qa = sb + offQ + kk*32;
                ldsm4(q_r[kk][0], q_r[kk][1], q_r[kk][2], q_r[kk][3], qa);
            }
        }
        if (p + 1 < npair){
            load_kv(2*p + 2);
            load_kv(2*p + 3);
        }
        compute_tile(2*p);
        compute_tile(2*p + 1);
    }

    // ---- epilogue: write single fp16 Y [M][768] ----
    const float inv0 = 1.f / l0, inv1 = 1.f / l1;
    const int bq = bh / H_, hh = bh % H_;
    const int t0 = qt*128 + w*16 + r;
    #pragma unroll
    for (int j2 = 0; j2 < 8; j2++){
        const int cc = hh*64 + j2*8 + c4*2;
        const size_t r0 = (size_t)(bq*T_ + t0    )*C_ + cc;
        const size_t r1 = (size_t)(bq*T_ + t0 + 8)*C_ + cc;
        *(uint32_t*)&g_Y[r0] = packhf(o[j2][0]*inv0, o[j2][1]*inv0);
        *(uint32_t*)&g_Y[r1] = packhf(o[j2][2]*inv1, o[j2][3]*inv1);
    }
}

// ---------------------------------------------------------------------------
extern "C" void kernel_launch(void* const* d_in, const int* in_sizes, int n_in,
                              void* d_out, int out_size)
{
    const float* x      = (const float*)d_in[0];
    const float* w_attn = (const float*)d_in[1];
    const float* b_attn = (const float*)d_in[2];
    const float* w_proj = (const float*)d_in[3];
    const float* b_proj = (const float*)d_in[4];
    float* out = (float*)d_out;

    cudaFuncSetAttribute(mma_gemm<1>, cudaFuncAttributeMaxDynamicSharedMemorySize, GEMM_SMEM);
    cudaFuncSetAttribute(mma_gemm<0>, cudaFuncAttributeMaxDynamicSharedMemorySize, GEMM_SMEM);
    cudaFuncSetAttribute(attn_tc, cudaFuncAttributeMaxDynamicSharedMemorySize, ATTN_SMEM);

    // 1) single fused prepass launch
    prepass<<<PB_TOT, 256>>>(x, w_attn, w_proj);

    // 2) QKV projection
    mma_gemm<1><<<dim3(3*C_/128, M_/128), 256, GEMM_SMEM>>>(b_attn, nullptr);

    // 3) attention
    attn_tc<<<dim3(T_/128, B_*H_), 256, ATTN_SMEM>>>();

    // 4) output projection
    mma_gemm<0><<<dim3(C_/128, M_/128), 256, GEMM_SMEM>>>(b_proj, out);
}